// round 10
// baseline (speedup 1.0000x reference)
#include <cuda_runtime.h>
#include <math_constants.h>

// MaxPlusDense: out[b,u] = max( max_i (x[b,i] - kernel[i,u]), bias[u] )
// B=256, D=1024, U=1024, fp32.
//
// Streaming-W design: X tile (8 rows, full D) lives in smem (loaded once,
// ONE barrier total); W is streamed from L2 via double-buffered LDG.128
// (__ldcg — smem eats the L1 carveout anyway). No split-K, no scratch,
// no atomics, no fences, no per-tile barriers.
// 1m x 4n microtile, 1024 CTAs x 64 threads -> ~14 warps/SM.

#define B_DIM 256
#define D_DIM 1024
#define U_DIM 1024

#define BM 8
#define BN 32
#define NT 64
#define PITCH 9          // xs row pitch in floats (bank-spread for STS, 36 KB total)
#define KBLK 8           // k-unroll block

__global__ __launch_bounds__(NT, 6) void maxplus_stream(
    const float* __restrict__ X,     // (B, D)
    const float* __restrict__ W,     // (D, U)
    const float* __restrict__ bias,  // (U,)
    float* __restrict__ out)         // (B, U)
{
    __shared__ float xs[D_DIM][PITCH];   // x^T tile: xs[k][m], 36 KB

    const int tid = threadIdx.x;
    const int bn  = blockIdx.x * BN;
    const int bm  = blockIdx.y * BM;

    // microtile: 1 row (m) x 4 cols (n)
    const int tm = tid & 7;            // 0..7
    const int tn = (tid >> 3) * 4;     // 0..28

    // ---- stage X tile (transposed) into smem — once ----
    {
        const int xm  = tid & 7;           // row
        const int xcb = (tid >> 3) * 4;    // col chunk base: 0,4,...,28
        const float* xrow = X + (size_t)(bm + xm) * D_DIM;
#pragma unroll
        for (int j = 0; j < D_DIM / 32; ++j) {   // 32 iters
            const int c = xcb + 32 * j;
            float4 v = __ldcg((const float4*)(xrow + c));
            xs[c + 0][xm] = v.x;
            xs[c + 1][xm] = v.y;
            xs[c + 2][xm] = v.z;
            xs[c + 3][xm] = v.w;
        }
    }
    __syncthreads();   // the only barrier in the kernel

    float acc0 = -CUDART_INF_F, acc1 = -CUDART_INF_F;
    float acc2 = -CUDART_INF_F, acc3 = -CUDART_INF_F;

    const float* wp = W + bn + tn;   // this thread's 4-wide W column slice

    // double-buffered W stream: two KBLK blocks in flight
    float4 buf0[KBLK], buf1[KBLK];

#pragma unroll
    for (int j = 0; j < KBLK; ++j)
        buf0[j] = __ldcg((const float4*)(wp + (size_t)j * U_DIM));

#pragma unroll 1
    for (int t = 0; t < D_DIM / KBLK; t += 2) {
        // prefetch block t+1 into buf1
#pragma unroll
        for (int j = 0; j < KBLK; ++j)
            buf1[j] = __ldcg((const float4*)(wp + (size_t)((t + 1) * KBLK + j) * U_DIM));

        // compute block t from buf0
#pragma unroll
        for (int j = 0; j < KBLK; ++j) {
            const float a = xs[t * KBLK + j][tm];
            acc0 = fmaxf(acc0, a - buf0[j].x);
            acc1 = fmaxf(acc1, a - buf0[j].y);
            acc2 = fmaxf(acc2, a - buf0[j].z);
            acc3 = fmaxf(acc3, a - buf0[j].w);
        }

        // prefetch block t+2 into buf0 (guarded on last iteration)
        if (t + 2 < D_DIM / KBLK) {
#pragma unroll
            for (int j = 0; j < KBLK; ++j)
                buf0[j] = __ldcg((const float4*)(wp + (size_t)((t + 2) * KBLK + j) * U_DIM));
        }

        // compute block t+1 from buf1
#pragma unroll
        for (int j = 0; j < KBLK; ++j) {
            const float a = xs[(t + 1) * KBLK + j][tm];
            acc0 = fmaxf(acc0, a - buf1[j].x);
            acc1 = fmaxf(acc1, a - buf1[j].y);
            acc2 = fmaxf(acc2, a - buf1[j].z);
            acc3 = fmaxf(acc3, a - buf1[j].w);
        }
    }

    // ---- epilogue: max with bias, one float4 store ----
    const float4 bv = *(const float4*)(bias + bn + tn);
    float4 o;
    o.x = fmaxf(acc0, bv.x);
    o.y = fmaxf(acc1, bv.y);
    o.z = fmaxf(acc2, bv.z);
    o.w = fmaxf(acc3, bv.w);
    *(float4*)(out + (size_t)(bm + tm) * U_DIM + bn + tn) = o;
}

extern "C" void kernel_launch(void* const* d_in, const int* in_sizes, int n_in,
                              void* d_out, int out_size)
{
    const float* x      = (const float*)d_in[0];   // (256, 1024)
    const float* kernel = (const float*)d_in[1];   // (1024, 1024)
    const float* bias   = (const float*)d_in[2];   // (1024,)
    float* out          = (float*)d_out;           // (256, 1024)

    dim3 grid(U_DIM / BN, B_DIM / BM);   // (32, 32) = 1024 CTAs
    maxplus_stream<<<grid, NT>>>(x, kernel, bias, out);
}

// round 11
// speedup vs baseline: 2.1108x; 2.1108x over previous
#include <cuda_runtime.h>
#include <math_constants.h>

// MaxPlusDense: out[b,u] = max( max_i (x[b,i] - kernel[i,u]), bias[u] )
// B=256, D=1024, U=1024, fp32.
//
// Scalar FADD+FMNMX core with SGEMM-style broadcast fragments:
// warp = 4(r) x 8(c); A frags at r*4 / 16+r*4 (1 wf each), B frag at c*4
// (128B contiguous, 1 wf). 8x4 microtile -> 2.09 instr/cell, 0.4 LDS-B/cell.
// Split-K=8, fused last-CTA reduction using atom.acq_rel (NO __threadfence ->
// no CCTL.IVALL L1 flushes).

#define B_DIM 256
#define D_DIM 1024
#define U_DIM 1024

#define SPLITS 8
#define KSEG   (D_DIM / SPLITS)   // 128
#define BM 64
#define BN 32
#define BK 16
#define NT 64
#define NTILES ((B_DIM / BM) * (U_DIM / BN))   // 4*32 = 128

__device__ float    g_scratch[SPLITS][B_DIM * U_DIM];   // 8 MB partials
__device__ unsigned g_cnt[NTILES];                      // monotonic counters

__device__ __forceinline__ unsigned atom_add_acqrel(unsigned* p, unsigned v) {
    unsigned old;
    asm volatile("atom.acq_rel.gpu.global.add.u32 %0, [%1], %2;"
                 : "=r"(old) : "l"(p), "r"(v) : "memory");
    return old;
}

__global__ __launch_bounds__(NT, 8) void maxplus_fused(
    const float* __restrict__ X,     // (B, D)
    const float* __restrict__ W,     // (D, U)
    const float* __restrict__ bias,  // (U,)
    float* __restrict__ out)         // (B, U)
{
    __shared__ __align__(16) float xs[BK][BM + 4];   // x^T tile: xs[k][m], pitch 68
    __shared__ __align__(16) float ws[BK][BN + 4];   // W tile:   ws[k][n], pitch 36
    __shared__ int s_last;

    const int tid   = threadIdx.x;
    const int lane  = tid & 31;
    const int wid   = tid >> 5;           // 0..1
    const int bn    = blockIdx.x * BN;
    const int bm    = blockIdx.y * BM;
    const int split = blockIdx.z;
    const int kbase = split * KSEG;

    // warp tile 32(m) x 32(n); lane = 4(r) x 8(c); microtile 8m x 4n
    const int wb = wid * 32;              // warp m-base
    const int r4 = (lane & 3) * 4;        // 0,4,8,12
    const int c4 = (lane >> 2) * 4;       // 0..28

    // gmem->smem staging (fully coalesced-ish)
    // X: 4 float4/thread: row xm + j*16, k-quad xk
    const int xm = tid >> 2;              // 0..15 (+ j*16)
    const int xk = (tid & 3) * 4;         // 0,4,8,12
    // W: 2 float4/thread: k-row wk + j*8, n-quad wn
    const int wk = tid >> 3;              // 0..7 (+ j*8)
    const int wn = (tid & 7) * 4;         // 0..28

    const float* xg = X + (size_t)(bm + xm) * D_DIM + kbase + xk;
    const float* wg = W + (size_t)(kbase + wk) * U_DIM + bn + wn;

    float acc[8][4];
#pragma unroll
    for (int i = 0; i < 8; i++)
#pragma unroll
        for (int j = 0; j < 4; j++) acc[i][j] = -CUDART_INF_F;

    // prologue: stage tile 0 in registers
    float4 xv[4], wv[2];
#pragma unroll
    for (int j = 0; j < 4; j++) xv[j] = *(const float4*)(xg + (size_t)j * 16 * D_DIM);
#pragma unroll
    for (int j = 0; j < 2; j++) wv[j] = *(const float4*)(wg + (size_t)j * 8 * U_DIM);

#pragma unroll 1
    for (int t = 0; t < KSEG / BK; t++) {
        // commit staged regs to smem (X transposed)
#pragma unroll
        for (int j = 0; j < 4; j++) {
            const int m = xm + j * 16;
            xs[xk + 0][m] = xv[j].x;
            xs[xk + 1][m] = xv[j].y;
            xs[xk + 2][m] = xv[j].z;
            xs[xk + 3][m] = xv[j].w;
        }
#pragma unroll
        for (int j = 0; j < 2; j++)
            *(float4*)&ws[wk + j * 8][wn] = wv[j];
        __syncthreads();

        // prefetch next tile (L2-resident)
        if (t + 1 < KSEG / BK) {
            const int ko = (t + 1) * BK;
#pragma unroll
            for (int j = 0; j < 4; j++)
                xv[j] = *(const float4*)(xg + ko + (size_t)j * 16 * D_DIM);
#pragma unroll
            for (int j = 0; j < 2; j++)
                wv[j] = *(const float4*)(wg + (size_t)(ko + j * 8) * U_DIM);
        }

#pragma unroll
        for (int kk = 0; kk < BK; kk++) {
            float4 A0 = *(const float4*)&xs[kk][wb + r4];        // rows 0-3   (1 wf)
            float4 A1 = *(const float4*)&xs[kk][wb + 16 + r4];   // rows 4-7   (1 wf)
            float4 Bv = *(const float4*)&ws[kk][c4];             // cols 0-3   (1 wf)

            float a[8] = {A0.x, A0.y, A0.z, A0.w, A1.x, A1.y, A1.z, A1.w};
            float b[4] = {Bv.x, Bv.y, Bv.z, Bv.w};
#pragma unroll
            for (int i = 0; i < 8; i++)
#pragma unroll
                for (int j = 0; j < 4; j++)
                    acc[i][j] = fmaxf(acc[i][j], a[i] - b[j]);
        }
        __syncthreads();
    }

    // ---- write split partials ----
    float* dst = g_scratch[split];
#pragma unroll
    for (int i = 0; i < 8; i++) {
        const int row = (i < 4) ? (wb + r4 + i) : (wb + 16 + r4 + i - 4);
        *(float4*)&dst[(size_t)(bm + row) * U_DIM + bn + c4] =
            make_float4(acc[i][0], acc[i][1], acc[i][2], acc[i][3]);
    }
    __syncthreads();   // all partial STGs happen-before tid0's release-atom

    // ---- last-arriving split reduces this tile ----
    if (tid == 0) {
        unsigned old = atom_add_acqrel(&g_cnt[blockIdx.y * (U_DIM / BN) + blockIdx.x], 1u);
        s_last = (((old + 1) & (SPLITS - 1)) == 0) ? 1 : 0;
    }
    __syncthreads();   // tid0's acquire happens-before all threads' reads

    if (s_last) {
        const float4 bv = *(const float4*)&bias[bn + c4];
#pragma unroll
        for (int i = 0; i < 8; i++) {
            const int row = (i < 4) ? (wb + r4 + i) : (wb + 16 + r4 + i - 4);
            const size_t off = (size_t)(bm + row) * U_DIM + bn + c4;
            float r0 = bv.x, r1 = bv.y, r2 = bv.z, r3 = bv.w;
#pragma unroll
            for (int s = 0; s < SPLITS; s++) {
                float4 p = __ldcg((const float4*)&g_scratch[s][off]);
                r0 = fmaxf(r0, p.x);
                r1 = fmaxf(r1, p.y);
                r2 = fmaxf(r2, p.z);
                r3 = fmaxf(r3, p.w);
            }
            *(float4*)&out[off] = make_float4(r0, r1, r2, r3);
        }
    }
}

extern "C" void kernel_launch(void* const* d_in, const int* in_sizes, int n_in,
                              void* d_out, int out_size)
{
    const float* x      = (const float*)d_in[0];   // (256, 1024)
    const float* kernel = (const float*)d_in[1];   // (1024, 1024)
    const float* bias   = (const float*)d_in[2];   // (1024,)
    float* out          = (float*)d_out;           // (256, 1024)

    dim3 grid(U_DIM / BN, B_DIM / BM, SPLITS);     // (32, 4, 8) = 1024 CTAs
    maxplus_fused<<<grid, NT>>>(x, kernel, bias, out);
}

// round 12
// speedup vs baseline: 2.1147x; 1.0018x over previous
#include <cuda_runtime.h>
#include <math_constants.h>

// MaxPlusDense: out[b,u] = max( max_i (x[b,i] - kernel[i,u]), bias[u] )
// B=256, D=1024, U=1024, fp32.
//
// R11 skeleton + two fixes:
//  1) NO local arrays in the hot loop (they compile to alu-pipe MOVs; R2 vs
//     R9/R11 pipe balance proves it). Accumulators = 8 named float4s, inner
//     loop = direct component macros.
//  2) Conflict-free X-transpose STS: per-store lanes span xm 0..15 x xk{0,4};
//     pitch 68 -> Dk=4 gives +16 bank offset -> disjoint halves, 1 wf/STS.

#define B_DIM 256
#define D_DIM 1024
#define U_DIM 1024

#define SPLITS 8
#define KSEG   (D_DIM / SPLITS)   // 128
#define BM 64
#define BN 32
#define BK 16
#define NT 64
#define NTILES ((B_DIM / BM) * (U_DIM / BN))   // 128

__device__ float    g_scratch[SPLITS][B_DIM * U_DIM];   // 8 MB partials
__device__ unsigned g_cnt[NTILES];                      // monotonic counters

__device__ __forceinline__ unsigned atom_add_acqrel(unsigned* p, unsigned v) {
    unsigned old;
    asm volatile("atom.acq_rel.gpu.global.add.u32 %0, [%1], %2;"
                 : "=r"(old) : "l"(p), "r"(v) : "memory");
    return old;
}

// one k-step contribution of A-component `ac` into accumulator row Q
#define MP_ROW(Q, ac)                        \
    Q.x = fmaxf(Q.x, (ac) - Bv.x);           \
    Q.y = fmaxf(Q.y, (ac) - Bv.y);           \
    Q.z = fmaxf(Q.z, (ac) - Bv.z);           \
    Q.w = fmaxf(Q.w, (ac) - Bv.w);

__global__ __launch_bounds__(NT, 8) void maxplus_fused(
    const float* __restrict__ X,     // (B, D)
    const float* __restrict__ W,     // (D, U)
    const float* __restrict__ bias,  // (U,)
    float* __restrict__ out)         // (B, U)
{
    __shared__ __align__(16) float xs[BK][BM + 4];   // x^T tile: xs[k][m], pitch 68
    __shared__ __align__(16) float ws[BK][BN + 4];   // W tile:   ws[k][n], pitch 36
    __shared__ int s_last;

    const int tid   = threadIdx.x;
    const int lane  = tid & 31;
    const int wid   = tid >> 5;           // 0..1
    const int bn    = blockIdx.x * BN;
    const int bm    = blockIdx.y * BM;
    const int split = blockIdx.z;
    const int kbase = split * KSEG;

    // warp tile 32(m) x 32(n); lane = 4(r) x 8(c); microtile 8m x 4n
    const int wb = wid * 32;              // warp m-base
    const int r4 = (lane & 3) * 4;        // 0,4,8,12
    const int c4 = (lane >> 2) * 4;       // 0..28

    // ---- staging maps ----
    // X: 4 float4/thread: rows xm, xm+32; k-quads x4, x4+8
    const int xm = tid >> 1;              // 0..31
    const int x4 = (tid & 1) * 4;         // 0 or 4
    // W: 2 float4/thread: k-rows wk, wk+8; n-quad wn
    const int wk = tid >> 3;              // 0..7
    const int wn = (tid & 7) * 4;         // 0..28

    const float* xg = X + (size_t)(bm + xm) * D_DIM + kbase + x4;
    const float* wg = W + (size_t)(kbase + wk) * U_DIM + bn + wn;

    float4 q0, q1, q2, q3, q4, q5, q6, q7;
    q0 = q1 = q2 = q3 = q4 = q5 = q6 = q7 =
        make_float4(-CUDART_INF_F, -CUDART_INF_F, -CUDART_INF_F, -CUDART_INF_F);

    // prologue: stage tile 0 in registers
    float4 xv00, xv01, xv10, xv11, wv0, wv1;
    xv00 = *(const float4*)(xg);                                   // (xm,    x4)
    xv01 = *(const float4*)(xg + 8);                               // (xm,    x4+8)
    xv10 = *(const float4*)(xg + (size_t)32 * D_DIM);              // (xm+32, x4)
    xv11 = *(const float4*)(xg + (size_t)32 * D_DIM + 8);          // (xm+32, x4+8)
    wv0  = *(const float4*)(wg);
    wv1  = *(const float4*)(wg + (size_t)8 * U_DIM);

#pragma unroll 1
    for (int t = 0; t < KSEG / BK; t++) {
        // ---- commit staged regs to smem (X transposed; conflict-free STS) ----
        xs[x4 + 0][xm] = xv00.x;  xs[x4 + 1][xm] = xv00.y;
        xs[x4 + 2][xm] = xv00.z;  xs[x4 + 3][xm] = xv00.w;
        xs[x4 + 8][xm] = xv01.x;  xs[x4 + 9][xm] = xv01.y;
        xs[x4 + 10][xm] = xv01.z; xs[x4 + 11][xm] = xv01.w;
        xs[x4 + 0][xm + 32] = xv10.x;  xs[x4 + 1][xm + 32] = xv10.y;
        xs[x4 + 2][xm + 32] = xv10.z;  xs[x4 + 3][xm + 32] = xv10.w;
        xs[x4 + 8][xm + 32] = xv11.x;  xs[x4 + 9][xm + 32] = xv11.y;
        xs[x4 + 10][xm + 32] = xv11.z; xs[x4 + 11][xm + 32] = xv11.w;
        *(float4*)&ws[wk][wn]     = wv0;
        *(float4*)&ws[wk + 8][wn] = wv1;
        __syncthreads();

        // ---- prefetch next tile (L2-resident) ----
        if (t + 1 < KSEG / BK) {
            const int ko = (t + 1) * BK;
            xv00 = *(const float4*)(xg + ko);
            xv01 = *(const float4*)(xg + ko + 8);
            xv10 = *(const float4*)(xg + ko + (size_t)32 * D_DIM);
            xv11 = *(const float4*)(xg + ko + (size_t)32 * D_DIM + 8);
            wv0  = *(const float4*)(wg + (size_t)ko * U_DIM);
            wv1  = *(const float4*)(wg + (size_t)(ko + 8) * U_DIM);
        }

        // ---- compute: 16 k-steps, direct components only ----
#pragma unroll
        for (int kk = 0; kk < BK; kk++) {
            const float4 A0 = *(const float4*)&xs[kk][wb + r4];        // rows 0-3
            const float4 A1 = *(const float4*)&xs[kk][wb + 16 + r4];   // rows 4-7
            const float4 Bv = *(const float4*)&ws[kk][c4];             // cols 0-3
            MP_ROW(q0, A0.x)
            MP_ROW(q1, A0.y)
            MP_ROW(q2, A0.z)
            MP_ROW(q3, A0.w)
            MP_ROW(q4, A1.x)
            MP_ROW(q5, A1.y)
            MP_ROW(q6, A1.z)
            MP_ROW(q7, A1.w)
        }
        __syncthreads();
    }

    // ---- write split partials ----
    {
        float* dst = g_scratch[split];
        const size_t base0 = (size_t)(bm + wb + r4) * U_DIM + bn + c4;
        const size_t base1 = (size_t)(bm + wb + 16 + r4) * U_DIM + bn + c4;
        *(float4*)&dst[base0]               = q0;
        *(float4*)&dst[base0 + U_DIM]       = q1;
        *(float4*)&dst[base0 + 2 * U_DIM]   = q2;
        *(float4*)&dst[base0 + 3 * U_DIM]   = q3;
        *(float4*)&dst[base1]               = q4;
        *(float4*)&dst[base1 + U_DIM]       = q5;
        *(float4*)&dst[base1 + 2 * U_DIM]   = q6;
        *(float4*)&dst[base1 + 3 * U_DIM]   = q7;
    }
    __syncthreads();   // partial STGs happen-before tid0's release-atom

    // ---- last-arriving split reduces this tile ----
    if (tid == 0) {
        unsigned old = atom_add_acqrel(&g_cnt[blockIdx.y * (U_DIM / BN) + blockIdx.x], 1u);
        s_last = (((old + 1) & (SPLITS - 1)) == 0) ? 1 : 0;
    }
    __syncthreads();   // tid0's acquire happens-before all threads' reads

    if (s_last) {
        const float4 bv = *(const float4*)&bias[bn + c4];
#pragma unroll
        for (int half = 0; half < 2; half++) {
            const int rowb = wb + half * 16 + r4;
#pragma unroll
            for (int i = 0; i < 4; i++) {
                const size_t off = (size_t)(bm + rowb + i) * U_DIM + bn + c4;
                float r0 = bv.x, r1 = bv.y, r2 = bv.z, r3 = bv.w;
#pragma unroll
                for (int s = 0; s < SPLITS; s++) {
                    const float4 p = __ldcg((const float4*)&g_scratch[s][off]);
                    r0 = fmaxf(r0, p.x);
                    r1 = fmaxf(r1, p.y);
                    r2 = fmaxf(r2, p.z);
                    r3 = fmaxf(r3, p.w);
                }
                *(float4*)&out[off] = make_float4(r0, r1, r2, r3);
            }
        }
    }
}

extern "C" void kernel_launch(void* const* d_in, const int* in_sizes, int n_in,
                              void* d_out, int out_size)
{
    const float* x      = (const float*)d_in[0];   // (256, 1024)
    const float* kernel = (const float*)d_in[1];   // (1024, 1024)
    const float* bias   = (const float*)d_in[2];   // (1024,)
    float* out          = (float*)d_out;           // (256, 1024)

    dim3 grid(U_DIM / BN, B_DIM / BM, SPLITS);     // (32, 4, 8) = 1024 CTAs
    maxplus_fused<<<grid, NT>>>(x, kernel, bias, out);
}